// round 15
// baseline (speedup 1.0000x reference)
#include <cuda_runtime.h>
#include <cuda_fp16.h>
#include <mma.h>
#include <cstdint>

using namespace nvcuda;

// Problem constants
constexpr int B = 32;
constexpr int L = 1024;
constexpr int D = 512;
constexpr float NEG_INF = -1000000000.0f;
constexpr float SCALE = 0.04419417382415922f; // 1/sqrt(512)

// __device__ scratch (allocation-guard-legal)
__device__ __half g_Qh[B * L * D];   // half-rounded query input
__device__ __half g_Kh[B * L * D];   // half-rounded key input
__device__ __half g_Wqh[D * D];      // half-rounded Wq
__device__ __half g_Wkh[D * D];      // half-rounded Wk
__device__ __half g_Q[B * L * D];    // relu(q@Wq+bq), half
__device__ __half g_K[B * L * D];    // relu(k@Wk+bk), half
__device__ float  g_S[B * L * L];    // masked scaled logits (fp32)

// ---------------------------------------------------------------------------
// cp.async helpers
// ---------------------------------------------------------------------------
__device__ __forceinline__ void cp_async16(void* smem_dst, const void* gmem_src) {
    unsigned int s = (unsigned int)__cvta_generic_to_shared(smem_dst);
    asm volatile("cp.async.cg.shared.global [%0], [%1], 16;\n" :: "r"(s), "l"(gmem_src));
}
__device__ __forceinline__ void cp_commit() {
    asm volatile("cp.async.commit_group;\n");
}
template <int N>
__device__ __forceinline__ void cp_wait() {
    asm volatile("cp.async.wait_group %0;\n" :: "n"(N));
}

__device__ __forceinline__ uint4 cvt_half8(const float4& a, const float4& b) {
    __half2 h0 = __floats2half2_rn(a.x, a.y);
    __half2 h1 = __floats2half2_rn(a.z, a.w);
    __half2 h2 = __floats2half2_rn(b.x, b.y);
    __half2 h3 = __floats2half2_rn(b.z, b.w);
    uint4 o;
    o.x = *(unsigned int*)&h0; o.y = *(unsigned int*)&h1;
    o.z = *(unsigned int*)&h2; o.w = *(unsigned int*)&h3;
    return o;
}

// ---------------------------------------------------------------------------
// round_half: dst = half_rn(src), 8 floats -> 8 halfs (16B store) per iter
// ---------------------------------------------------------------------------
__global__ __launch_bounds__(256)
void round_half(const float* __restrict__ src, __half* __restrict__ dst, int n8) {
    int i = blockIdx.x * blockDim.x + threadIdx.x;
    int stride = gridDim.x * blockDim.x;
    for (; i < n8; i += stride) {
        float4 a = ((const float4*)src)[2 * i];
        float4 b = ((const float4*)src)[2 * i + 1];
        ((uint4*)dst)[i] = cvt_half8(a, b);
    }
}

// round_w: both weight matrices in one launch (blockIdx.y selects)
__global__ __launch_bounds__(256)
void round_w(const float* __restrict__ Wq, const float* __restrict__ Wk, int n8) {
    const float* src = blockIdx.y == 0 ? Wq : Wk;
    __half* dst = blockIdx.y == 0 ? g_Wqh : g_Wkh;
    int i = blockIdx.x * blockDim.x + threadIdx.x;
    int stride = gridDim.x * blockDim.x;
    for (; i < n8; i += stride) {
        float4 a = ((const float4*)src)[2 * i];
        float4 b = ((const float4*)src)[2 * i + 1];
        ((uint4*)dst)[i] = cvt_half8(a, b);
    }
}

// ---------------------------------------------------------------------------
// proj (R12-proven form): out = half_rn(relu(in @ W + bias))
// CTA 128x128, 256 threads (8 warps), warp 32x64, fp16 wmma m16n16k16.
// 2-stage cp.async double buffer, TK=32 halfs. Separate launch per matrix.
// SMEM (halfs): A0@0, A1@5120 (128x40), B0@10240, B1@14592 (32x136);
// epilogue Cs f32 128x132 overlays. SMEM = 67584 B, 2 CTAs/SM.
// ---------------------------------------------------------------------------
constexpr int GEMM_SMEM_BYTES = 128 * 132 * 4;  // 67584

template <bool TO_Q>
__global__ __launch_bounds__(256, 2)
void proj_kernel(const float* __restrict__ bias) {
    extern __shared__ __align__(128) char smem_raw[];
    __half* smh = (__half*)smem_raw;
    float*  Cs  = (float*)smem_raw;   // epilogue overlay

    const __half* in = TO_Q ? g_Qh : g_Kh;
    const __half* W  = TO_Q ? g_Wqh : g_Wkh;
    __half* out      = TO_Q ? g_Q : g_K;

    const int tid  = threadIdx.x;
    const int warp = tid >> 5;
    const int m0 = blockIdx.y * 128;
    const int n0 = blockIdx.x * 128;

    const int wr = (warp >> 1) * 32;   // 0,32,64,96
    const int wc = (warp & 1) * 64;    // 0,64

    const __half* Ain = in + (size_t)m0 * D;

    auto stage = [&](int kt) {
        const int pb = kt & 1;
        const int k0 = kt * 32;
        __half* Ab = smh + pb * 5120;           // 128 x ld40
        __half* Bb = smh + 10240 + pb * 4352;   // 32 x ld136
        #pragma unroll
        for (int i = 0; i < 2; i++) {           // A: 512 chunks of 8 halfs
            int idx = tid + i * 256;
            int r = idx >> 2, c8 = (idx & 3) << 3;
            cp_async16(&Ab[r * 40 + c8], Ain + (size_t)r * D + k0 + c8);
        }
        #pragma unroll
        for (int i = 0; i < 2; i++) {           // B: 512 chunks
            int idx = tid + i * 256;
            int r = idx >> 4, c8 = (idx & 15) << 3;
            cp_async16(&Bb[r * 136 + c8], W + (size_t)(k0 + r) * D + n0 + c8);
        }
        cp_commit();
    };

    wmma::fragment<wmma::accumulator, 16, 16, 16, float> acc[2][4];
    #pragma unroll
    for (int i = 0; i < 2; i++)
        #pragma unroll
        for (int j = 0; j < 4; j++) wmma::fill_fragment(acc[i][j], 0.0f);

    stage(0);
    for (int kt = 0; kt < 16; kt++) {
        const int pb = kt & 1;
        if (kt < 15) { stage(kt + 1); cp_wait<1>(); }
        else         { cp_wait<0>(); }
        __syncthreads();

        const __half* Ab = smh + pb * 5120;
        const __half* Bb = smh + 10240 + pb * 4352;
        #pragma unroll
        for (int k16 = 0; k16 < 2; k16++) {
            wmma::fragment<wmma::matrix_a, 16, 16, 16, __half, wmma::row_major> a[2];
            #pragma unroll
            for (int i = 0; i < 2; i++)
                wmma::load_matrix_sync(a[i], &Ab[(wr + i * 16) * 40 + k16 * 16], 40);
            #pragma unroll
            for (int j = 0; j < 4; j++) {
                wmma::fragment<wmma::matrix_b, 16, 16, 16, __half, wmma::row_major> bf;
                wmma::load_matrix_sync(bf, &Bb[(k16 * 16) * 136 + wc + j * 16], 136);
                #pragma unroll
                for (int i = 0; i < 2; i++)
                    wmma::mma_sync(acc[i][j], a[i], bf, acc[i][j]);
            }
        }
        __syncthreads();
    }

    // Epilogue: accs -> Cs (f32 overlay) -> bias+relu -> half -> global
    #pragma unroll
    for (int i = 0; i < 2; i++)
        #pragma unroll
        for (int j = 0; j < 4; j++)
            wmma::store_matrix_sync(&Cs[(wr + i * 16) * 132 + wc + j * 16],
                                    acc[i][j], 132, wmma::mem_row_major);
    __syncthreads();

    for (int i = tid; i < 128 * 128 / 8; i += 256) {
        int idx = i << 3;
        int r = idx >> 7, c = idx & 127;
        float4 v0 = *(const float4*)&Cs[r * 132 + c];
        float4 v1 = *(const float4*)&Cs[r * 132 + c + 4];
        const float* bp = &bias[n0 + c];
        float4 u0 = make_float4(fmaxf(v0.x + bp[0], 0.0f), fmaxf(v0.y + bp[1], 0.0f),
                                fmaxf(v0.z + bp[2], 0.0f), fmaxf(v0.w + bp[3], 0.0f));
        float4 u1 = make_float4(fmaxf(v1.x + bp[4], 0.0f), fmaxf(v1.y + bp[5], 0.0f),
                                fmaxf(v1.z + bp[6], 0.0f), fmaxf(v1.w + bp[7], 0.0f));
        *(uint4*)&out[(size_t)(m0 + r) * D + n0 + c] = cvt_half8(u0, u1);
    }
}

// ---------------------------------------------------------------------------
// logits: S[b,m,n] = (Q[b,m,:].K[b,n,:])*SCALE + (key_mask[b,n]?0:NEG)
// CTA 128 queries x 128 keys, 256 threads, warp 32x64, fp16 wmma.
// 3-stage cp.async pipeline; K^T as col_major b-fragment over row-major K.
// SMEM (halfs): Qs0..2 @ {0,5120,10240}, Ks0..2 @ {15360,20480,25600}
// (each 128x40); epilogue Cs f32 128x132 overlays. SMEM = 67584 B.
// Grid (8,8,32): batch outer for L2 reuse.
// ---------------------------------------------------------------------------
__global__ __launch_bounds__(256, 2)
void logits_kernel(const int* __restrict__ key_mask) {
    extern __shared__ __align__(128) char smem_raw[];
    __half* smh = (__half*)smem_raw;
    float*  Cs  = (float*)smem_raw;

    const int tid  = threadIdx.x;
    const int warp = tid >> 5;
    const int b  = blockIdx.z;
    const int m0 = blockIdx.y * 128;
    const int n0 = blockIdx.x * 128;

    const int wr = (warp >> 1) * 32;
    const int wc = (warp & 1) * 64;

    const __half* Qg = g_Q + ((size_t)b * L + m0) * D;
    const __half* Kg = g_K + ((size_t)b * L + n0) * D;

    auto stage = [&](int kt) {
        const int sb = kt % 3;
        const int k0 = kt * 32;
        __half* Qb = smh + sb * 5120;
        __half* Kb = smh + 15360 + sb * 5120;
        #pragma unroll
        for (int i = 0; i < 2; i++) {
            int idx = tid + i * 256;
            int r = idx >> 2, c8 = (idx & 3) << 3;
            cp_async16(&Qb[r * 40 + c8], Qg + (size_t)r * D + k0 + c8);
        }
        #pragma unroll
        for (int i = 0; i < 2; i++) {
            int idx = tid + i * 256;
            int r = idx >> 2, c8 = (idx & 3) << 3;
            cp_async16(&Kb[r * 40 + c8], Kg + (size_t)r * D + k0 + c8);
        }
        cp_commit();
    };

    wmma::fragment<wmma::accumulator, 16, 16, 16, float> acc[2][4];
    #pragma unroll
    for (int i = 0; i < 2; i++)
        #pragma unroll
        for (int j = 0; j < 4; j++) wmma::fill_fragment(acc[i][j], 0.0f);

    stage(0);
    stage(1);
    for (int kt = 0; kt < 16; kt++) {
        if (kt < 14) { stage(kt + 2); cp_wait<2>(); }
        else if (kt == 14) { cp_wait<1>(); }
        else { cp_wait<0>(); }
        __syncthreads();

        const int sb = kt % 3;
        const __half* Qb = smh + sb * 5120;
        const __half* Kb = smh + 15360 + sb * 5120;
        #pragma unroll
        for (int k16 = 0; k16 < 2; k16++) {
            wmma::fragment<wmma::matrix_a, 16, 16, 16, __half, wmma::row_major> a[2];
            #pragma unroll
            for (int i = 0; i < 2; i++)
                wmma::load_matrix_sync(a[i], &Qb[(wr + i * 16) * 40 + k16 * 16], 40);
            #pragma unroll
            for (int j = 0; j < 4; j++) {
                // B = K^T slice: col-major view of row-major K tile
                wmma::fragment<wmma::matrix_b, 16, 16, 16, __half, wmma::col_major> bf;
                wmma::load_matrix_sync(bf, &Kb[(wc + j * 16) * 40 + k16 * 16], 40);
                #pragma unroll
                for (int i = 0; i < 2; i++)
                    wmma::mma_sync(acc[i][j], a[i], bf, acc[i][j]);
            }
        }
        __syncthreads();
    }

    #pragma unroll
    for (int i = 0; i < 2; i++)
        #pragma unroll
        for (int j = 0; j < 4; j++)
            wmma::store_matrix_sync(&Cs[(wr + i * 16) * 132 + wc + j * 16],
                                    acc[i][j], 132, wmma::mem_row_major);
    __syncthreads();

    // Epilogue: scale + key-mask bias -> g_S (fp32)
    const int* km = key_mask + (size_t)b * L + n0;
    for (int i = tid; i < 128 * 128 / 4; i += 256) {
        int idx = i << 2;
        int r = idx >> 7, c = idx & 127;
        float4 v = *(const float4*)&Cs[r * 132 + c];
        v.x = fmaf(v.x, SCALE, km[c + 0] ? 0.0f : NEG_INF);
        v.y = fmaf(v.y, SCALE, km[c + 1] ? 0.0f : NEG_INF);
        v.z = fmaf(v.z, SCALE, km[c + 2] ? 0.0f : NEG_INF);
        v.w = fmaf(v.w, SCALE, km[c + 3] ? 0.0f : NEG_INF);
        *(float4*)&g_S[((size_t)b * L + m0 + r) * L + n0 + c] = v;
    }
}

// ---------------------------------------------------------------------------
// softmax: per-row (1024 keys) register-resident softmax * query_mask
// 256 threads = 8 warps, 1 row per warp, 32 floats per lane.
// ---------------------------------------------------------------------------
__global__ __launch_bounds__(256)
void softmax_kernel(const int* __restrict__ query_mask,
                    float* __restrict__ out) {
    const int lane = threadIdx.x & 31;
    const int warp = threadIdx.x >> 5;
    const size_t row = (size_t)blockIdx.x * 8 + warp;

    const float4* srow = (const float4*)(g_S + row * L);
    float4 v[8];
    #pragma unroll
    for (int j = 0; j < 8; j++) v[j] = srow[lane + j * 32];

    float mx = -3.4e38f;
    #pragma unroll
    for (int j = 0; j < 8; j++)
        mx = fmaxf(mx, fmaxf(fmaxf(v[j].x, v[j].y), fmaxf(v[j].z, v[j].w)));
    #pragma unroll
    for (int o = 16; o > 0; o >>= 1) mx = fmaxf(mx, __shfl_xor_sync(0xffffffffu, mx, o));

    float sum = 0.0f;
    #pragma unroll
    for (int j = 0; j < 8; j++) {
        v[j].x = __expf(v[j].x - mx);
        v[j].y = __expf(v[j].y - mx);
        v[j].z = __expf(v[j].z - mx);
        v[j].w = __expf(v[j].w - mx);
        sum += (v[j].x + v[j].y) + (v[j].z + v[j].w);
    }
    #pragma unroll
    for (int o = 16; o > 0; o >>= 1) sum += __shfl_xor_sync(0xffffffffu, sum, o);

    const float inv = (float)query_mask[row] / sum;  // sum >= 1

    float4* orow = (float4*)(out + row * L);
    #pragma unroll
    for (int j = 0; j < 8; j++) {
        v[j].x *= inv; v[j].y *= inv; v[j].z *= inv; v[j].w *= inv;
        orow[lane + j * 32] = v[j];
    }
}

// ---------------------------------------------------------------------------
// kernel_launch — graph-capturable, allocation-free.
// 7 launches/iter so ncu (-s 5 -c 1) lands on logits_kernel.
// ---------------------------------------------------------------------------
extern "C" void kernel_launch(void* const* d_in, const int* in_sizes, int n_in,
                              void* d_out, int out_size) {
    (void)in_sizes; (void)n_in; (void)out_size;
    const float* query = (const float*)d_in[0];
    const float* key   = (const float*)d_in[1];
    const int*   qmask = (const int*)d_in[2];
    const int*   kmask = (const int*)d_in[3];
    const float* Wq    = (const float*)d_in[4];
    const float* bq    = (const float*)d_in[5];
    const float* Wk    = (const float*)d_in[6];
    const float* bk    = (const float*)d_in[7];
    float* out = (float*)d_out;

    static __half *d_Qh = nullptr, *d_Kh;
    if (!d_Qh) {
        cudaFuncSetAttribute(proj_kernel<true>,
                             cudaFuncAttributeMaxDynamicSharedMemorySize, GEMM_SMEM_BYTES);
        cudaFuncSetAttribute(proj_kernel<false>,
                             cudaFuncAttributeMaxDynamicSharedMemorySize, GEMM_SMEM_BYTES);
        cudaFuncSetAttribute(logits_kernel,
                             cudaFuncAttributeMaxDynamicSharedMemorySize, GEMM_SMEM_BYTES);
        cudaGetSymbolAddress((void**)&d_Kh, g_Kh);
        cudaGetSymbolAddress((void**)&d_Qh, g_Qh);  // last: guards the block
    }

    // 1) round inputs + weights to fp16 (RN) — 3 launches
    const int nQK8 = B * L * D / 8;   // 2,097,152
    const int nW8  = D * D / 8;       // 32,768
    round_half<<<1184, 256>>>(query, d_Qh, nQK8);
    round_half<<<1184, 256>>>(key,   d_Kh, nQK8);
    round_w<<<dim3(128, 2), 256>>>(Wq, Wk, nW8);

    // 2) projections — separate launches (R12-proven fast form)
    dim3 pgrid(D / 128, (B * L) / 128);  // (4, 256)
    proj_kernel<true ><<<pgrid, 256, GEMM_SMEM_BYTES>>>(bq);
    proj_kernel<false><<<pgrid, 256, GEMM_SMEM_BYTES>>>(bk);

    // 3) masked scaled logits (3-stage pipeline)
    logits_kernel<<<dim3(L / 128, L / 128, B), 256, GEMM_SMEM_BYTES>>>(kmask);

    // 4) softmax + query mask
    softmax_kernel<<<(B * L) / 8, 256>>>(qmask, out);
}

// round 16
// speedup vs baseline: 1.0022x; 1.0022x over previous
#include <cuda_runtime.h>
#include <cuda_fp16.h>
#include <mma.h>
#include <cstdint>

using namespace nvcuda;

// Problem constants
constexpr int B = 32;
constexpr int L = 1024;
constexpr int D = 512;
constexpr float NEG_INF = -1000000000.0f;
constexpr float SCALE = 0.04419417382415922f; // 1/sqrt(512)

// __device__ scratch (allocation-guard-legal)
__device__ __half g_Qh[B * L * D];   // half-rounded query input
__device__ __half g_Kh[B * L * D];   // half-rounded key input
__device__ __half g_Wqt[D * D];      // half-rounded Wq^T  (Wt[n][k] = W[k][n])
__device__ __half g_Wkt[D * D];      // half-rounded Wk^T
__device__ __half g_Q[B * L * D];    // relu(q@Wq+bq), half
__device__ __half g_K[B * L * D];    // relu(k@Wk+bk), half
__device__ float  g_S[B * L * L];    // masked scaled logits (fp32)

// ---------------------------------------------------------------------------
// cp.async helpers
// ---------------------------------------------------------------------------
__device__ __forceinline__ void cp_async16(void* smem_dst, const void* gmem_src) {
    unsigned int s = (unsigned int)__cvta_generic_to_shared(smem_dst);
    asm volatile("cp.async.cg.shared.global [%0], [%1], 16;\n" :: "r"(s), "l"(gmem_src));
}
__device__ __forceinline__ void cp_commit() {
    asm volatile("cp.async.commit_group;\n");
}
template <int N>
__device__ __forceinline__ void cp_wait() {
    asm volatile("cp.async.wait_group %0;\n" :: "n"(N));
}

__device__ __forceinline__ uint4 cvt_half8(const float4& a, const float4& b) {
    __half2 h0 = __floats2half2_rn(a.x, a.y);
    __half2 h1 = __floats2half2_rn(a.z, a.w);
    __half2 h2 = __floats2half2_rn(b.x, b.y);
    __half2 h3 = __floats2half2_rn(b.z, b.w);
    uint4 o;
    o.x = *(unsigned int*)&h0; o.y = *(unsigned int*)&h1;
    o.z = *(unsigned int*)&h2; o.w = *(unsigned int*)&h3;
    return o;
}

// ---------------------------------------------------------------------------
// round_qk: both inputs in one launch (grid.y selects query/key)
// ---------------------------------------------------------------------------
__global__ __launch_bounds__(256)
void round_qk(const float* __restrict__ q, const float* __restrict__ k, int n8) {
    const float* src = blockIdx.y == 0 ? q : k;
    __half* dst = blockIdx.y == 0 ? g_Qh : g_Kh;
    int i = blockIdx.x * blockDim.x + threadIdx.x;
    int stride = gridDim.x * blockDim.x;
    for (; i < n8; i += stride) {
        float4 a = ((const float4*)src)[2 * i];
        float4 b = ((const float4*)src)[2 * i + 1];
        ((uint4*)dst)[i] = cvt_half8(a, b);
    }
}

// ---------------------------------------------------------------------------
// round_wT: Wt[n][k] = half_rn(W[k][n]) for both weights (grid.z selects).
// 32x32 SMEM tile transpose; numerics identical to plain rounding.
// ---------------------------------------------------------------------------
__global__ __launch_bounds__(256)
void round_wT(const float* __restrict__ Wq, const float* __restrict__ Wk) {
    __shared__ float t[32][33];
    const float* W = blockIdx.z == 0 ? Wq : Wk;
    __half* Wt = blockIdx.z == 0 ? g_Wqt : g_Wkt;
    const int bx = blockIdx.x * 32;   // n-tile
    const int by = blockIdx.y * 32;   // k-tile
    const int tx = threadIdx.x & 31;
    const int ty = (threadIdx.x >> 5) * 4;
    #pragma unroll
    for (int i = 0; i < 4; i++)
        t[ty + i][tx] = W[(size_t)(by + ty + i) * D + bx + tx];
    __syncthreads();
    #pragma unroll
    for (int i = 0; i < 4; i++)
        Wt[(size_t)(bx + ty + i) * D + by + tx] = __float2half_rn(t[tx][ty + i]);
}

// ---------------------------------------------------------------------------
// proj (merged, grid.z selects Q/K): out = half_rn(relu(in @ W + bias))
// B-path now IDENTICAL to logits: Wt rows staged n-major (128x40 ld),
// col-major b-fragments. CTA 128x128, 256 threads, warp 32x64, 2-stage.
// SMEM (halfs): A0@0, A1@5120, B0@10240, B1@15360 (each 128x40);
// epilogue Cs f32 128x132 overlays. SMEM = 67584 B, 2 CTAs/SM.
// ---------------------------------------------------------------------------
constexpr int GEMM_SMEM_BYTES = 128 * 132 * 4;  // 67584

__global__ __launch_bounds__(256, 2)
void proj_kernel(const float* __restrict__ bq, const float* __restrict__ bk) {
    extern __shared__ __align__(128) char smem_raw[];
    __half* smh = (__half*)smem_raw;
    float*  Cs  = (float*)smem_raw;   // epilogue overlay

    const bool isQ = (blockIdx.z == 0);
    const __half* in   = isQ ? g_Qh : g_Kh;
    const __half* Wt   = isQ ? g_Wqt : g_Wkt;
    const float*  bias = isQ ? bq : bk;
    __half* out        = isQ ? g_Q : g_K;

    const int tid  = threadIdx.x;
    const int warp = tid >> 5;
    const int m0 = blockIdx.y * 128;
    const int n0 = blockIdx.x * 128;

    const int wr = (warp >> 1) * 32;   // 0,32,64,96
    const int wc = (warp & 1) * 64;    // 0,64

    const __half* Ag = in + (size_t)m0 * D;
    const __half* Bg = Wt + (size_t)n0 * D;

    auto stage = [&](int kt) {
        const int pb = kt & 1;
        const int k0 = kt * 32;
        __half* Ab = smh + pb * 5120;            // 128 x ld40
        __half* Bb = smh + 10240 + pb * 5120;    // 128 x ld40
        #pragma unroll
        for (int i = 0; i < 2; i++) {
            int idx = tid + i * 256;
            int r = idx >> 2, c8 = (idx & 3) << 3;
            cp_async16(&Ab[r * 40 + c8], Ag + (size_t)r * D + k0 + c8);
        }
        #pragma unroll
        for (int i = 0; i < 2; i++) {
            int idx = tid + i * 256;
            int r = idx >> 2, c8 = (idx & 3) << 3;
            cp_async16(&Bb[r * 40 + c8], Bg + (size_t)r * D + k0 + c8);
        }
        cp_commit();
    };

    wmma::fragment<wmma::accumulator, 16, 16, 16, float> acc[2][4];
    #pragma unroll
    for (int i = 0; i < 2; i++)
        #pragma unroll
        for (int j = 0; j < 4; j++) wmma::fill_fragment(acc[i][j], 0.0f);

    stage(0);
    for (int kt = 0; kt < 16; kt++) {
        const int pb = kt & 1;
        if (kt < 15) { stage(kt + 1); cp_wait<1>(); }
        else         { cp_wait<0>(); }
        __syncthreads();

        const __half* Ab = smh + pb * 5120;
        const __half* Bb = smh + 10240 + pb * 5120;
        #pragma unroll
        for (int k16 = 0; k16 < 2; k16++) {
            wmma::fragment<wmma::matrix_a, 16, 16, 16, __half, wmma::row_major> a[2];
            #pragma unroll
            for (int i = 0; i < 2; i++)
                wmma::load_matrix_sync(a[i], &Ab[(wr + i * 16) * 40 + k16 * 16], 40);
            #pragma unroll
            for (int j = 0; j < 4; j++) {
                // B = W slice: col-major view of n-major Wt tile (as in logits)
                wmma::fragment<wmma::matrix_b, 16, 16, 16, __half, wmma::col_major> bf;
                wmma::load_matrix_sync(bf, &Bb[(wc + j * 16) * 40 + k16 * 16], 40);
                #pragma unroll
                for (int i = 0; i < 2; i++)
                    wmma::mma_sync(acc[i][j], a[i], bf, acc[i][j]);
            }
        }
        __syncthreads();
    }

    // Epilogue: accs -> Cs (f32 overlay) -> bias+relu -> half -> global
    #pragma unroll
    for (int i = 0; i < 2; i++)
        #pragma unroll
        for (int j = 0; j < 4; j++)
            wmma::store_matrix_sync(&Cs[(wr + i * 16) * 132 + wc + j * 16],
                                    acc[i][j], 132, wmma::mem_row_major);
    __syncthreads();

    for (int i = tid; i < 128 * 128 / 8; i += 256) {
        int idx = i << 3;
        int r = idx >> 7, c = idx & 127;
        float4 v0 = *(const float4*)&Cs[r * 132 + c];
        float4 v1 = *(const float4*)&Cs[r * 132 + c + 4];
        const float* bp = &bias[n0 + c];
        float4 u0 = make_float4(fmaxf(v0.x + bp[0], 0.0f), fmaxf(v0.y + bp[1], 0.0f),
                                fmaxf(v0.z + bp[2], 0.0f), fmaxf(v0.w + bp[3], 0.0f));
        float4 u1 = make_float4(fmaxf(v1.x + bp[4], 0.0f), fmaxf(v1.y + bp[5], 0.0f),
                                fmaxf(v1.z + bp[6], 0.0f), fmaxf(v1.w + bp[7], 0.0f));
        *(uint4*)&out[(size_t)(m0 + r) * D + n0 + c] = cvt_half8(u0, u1);
    }
}

// ---------------------------------------------------------------------------
// logits: S[b,m,n] = (Q[b,m,:].K[b,n,:])*SCALE + (key_mask[b,n]?0:NEG)
// CTA 128x128, 256 threads, warp 32x64, 3-stage cp.async.
// SMEM (halfs): Qs0..2 @ {0,5120,10240}, Ks0..2 @ {15360,20480,25600};
// epilogue Cs f32 128x132 overlays. Grid (8,8,32).
// ---------------------------------------------------------------------------
__global__ __launch_bounds__(256, 2)
void logits_kernel(const int* __restrict__ key_mask) {
    extern __shared__ __align__(128) char smem_raw[];
    __half* smh = (__half*)smem_raw;
    float*  Cs  = (float*)smem_raw;

    const int tid  = threadIdx.x;
    const int warp = tid >> 5;
    const int b  = blockIdx.z;
    const int m0 = blockIdx.y * 128;
    const int n0 = blockIdx.x * 128;

    const int wr = (warp >> 1) * 32;
    const int wc = (warp & 1) * 64;

    const __half* Qg = g_Q + ((size_t)b * L + m0) * D;
    const __half* Kg = g_K + ((size_t)b * L + n0) * D;

    auto stage = [&](int kt) {
        const int sb = kt % 3;
        const int k0 = kt * 32;
        __half* Qb = smh + sb * 5120;
        __half* Kb = smh + 15360 + sb * 5120;
        #pragma unroll
        for (int i = 0; i < 2; i++) {
            int idx = tid + i * 256;
            int r = idx >> 2, c8 = (idx & 3) << 3;
            cp_async16(&Qb[r * 40 + c8], Qg + (size_t)r * D + k0 + c8);
        }
        #pragma unroll
        for (int i = 0; i < 2; i++) {
            int idx = tid + i * 256;
            int r = idx >> 2, c8 = (idx & 3) << 3;
            cp_async16(&Kb[r * 40 + c8], Kg + (size_t)r * D + k0 + c8);
        }
        cp_commit();
    };

    wmma::fragment<wmma::accumulator, 16, 16, 16, float> acc[2][4];
    #pragma unroll
    for (int i = 0; i < 2; i++)
        #pragma unroll
        for (int j = 0; j < 4; j++) wmma::fill_fragment(acc[i][j], 0.0f);

    stage(0);
    stage(1);
    for (int kt = 0; kt < 16; kt++) {
        if (kt < 14) { stage(kt + 2); cp_wait<2>(); }
        else if (kt == 14) { cp_wait<1>(); }
        else { cp_wait<0>(); }
        __syncthreads();

        const int sb = kt % 3;
        const __half* Qb = smh + sb * 5120;
        const __half* Kb = smh + 15360 + sb * 5120;
        #pragma unroll
        for (int k16 = 0; k16 < 2; k16++) {
            wmma::fragment<wmma::matrix_a, 16, 16, 16, __half, wmma::row_major> a[2];
            #pragma unroll
            for (int i = 0; i < 2; i++)
                wmma::load_matrix_sync(a[i], &Qb[(wr + i * 16) * 40 + k16 * 16], 40);
            #pragma unroll
            for (int j = 0; j < 4; j++) {
                wmma::fragment<wmma::matrix_b, 16, 16, 16, __half, wmma::col_major> bf;
                wmma::load_matrix_sync(bf, &Kb[(wc + j * 16) * 40 + k16 * 16], 40);
                #pragma unroll
                for (int i = 0; i < 2; i++)
                    wmma::mma_sync(acc[i][j], a[i], bf, acc[i][j]);
            }
        }
        __syncthreads();
    }

    #pragma unroll
    for (int i = 0; i < 2; i++)
        #pragma unroll
        for (int j = 0; j < 4; j++)
            wmma::store_matrix_sync(&Cs[(wr + i * 16) * 132 + wc + j * 16],
                                    acc[i][j], 132, wmma::mem_row_major);
    __syncthreads();

    // Epilogue: scale + key-mask bias -> g_S (fp32)
    const int* km = key_mask + (size_t)b * L + n0;
    for (int i = tid; i < 128 * 128 / 4; i += 256) {
        int idx = i << 2;
        int r = idx >> 7, c = idx & 127;
        float4 v = *(const float4*)&Cs[r * 132 + c];
        v.x = fmaf(v.x, SCALE, km[c + 0] ? 0.0f : NEG_INF);
        v.y = fmaf(v.y, SCALE, km[c + 1] ? 0.0f : NEG_INF);
        v.z = fmaf(v.z, SCALE, km[c + 2] ? 0.0f : NEG_INF);
        v.w = fmaf(v.w, SCALE, km[c + 3] ? 0.0f : NEG_INF);
        *(float4*)&g_S[((size_t)b * L + m0 + r) * L + n0 + c] = v;
    }
}

// ---------------------------------------------------------------------------
// softmax: per-row (1024 keys) register-resident softmax * query_mask
// ---------------------------------------------------------------------------
__global__ __launch_bounds__(256)
void softmax_kernel(const int* __restrict__ query_mask,
                    float* __restrict__ out) {
    const int lane = threadIdx.x & 31;
    const int warp = threadIdx.x >> 5;
    const size_t row = (size_t)blockIdx.x * 8 + warp;

    const float4* srow = (const float4*)(g_S + row * L);
    float4 v[8];
    #pragma unroll
    for (int j = 0; j < 8; j++) v[j] = srow[lane + j * 32];

    float mx = -3.4e38f;
    #pragma unroll
    for (int j = 0; j < 8; j++)
        mx = fmaxf(mx, fmaxf(fmaxf(v[j].x, v[j].y), fmaxf(v[j].z, v[j].w)));
    #pragma unroll
    for (int o = 16; o > 0; o >>= 1) mx = fmaxf(mx, __shfl_xor_sync(0xffffffffu, mx, o));

    float sum = 0.0f;
    #pragma unroll
    for (int j = 0; j < 8; j++) {
        v[j].x = __expf(v[j].x - mx);
        v[j].y = __expf(v[j].y - mx);
        v[j].z = __expf(v[j].z - mx);
        v[j].w = __expf(v[j].w - mx);
        sum += (v[j].x + v[j].y) + (v[j].z + v[j].w);
    }
    #pragma unroll
    for (int o = 16; o > 0; o >>= 1) sum += __shfl_xor_sync(0xffffffffu, sum, o);

    const float inv = (float)query_mask[row] / sum;  // sum >= 1

    float4* orow = (float4*)(out + row * L);
    #pragma unroll
    for (int j = 0; j < 8; j++) {
        v[j].x *= inv; v[j].y *= inv; v[j].z *= inv; v[j].w *= inv;
        orow[lane + j * 32] = v[j];
    }
}

// ---------------------------------------------------------------------------
// kernel_launch — graph-capturable, allocation-free.
// 5 launches: round_qk(0), round_wT(1), proj(2), logits(3)<-ncu, softmax(4).
// ---------------------------------------------------------------------------
extern "C" void kernel_launch(void* const* d_in, const int* in_sizes, int n_in,
                              void* d_out, int out_size) {
    (void)in_sizes; (void)n_in; (void)out_size;
    const float* query = (const float*)d_in[0];
    const float* key   = (const float*)d_in[1];
    const int*   qmask = (const int*)d_in[2];
    const int*   kmask = (const int*)d_in[3];
    const float* Wq    = (const float*)d_in[4];
    const float* bq    = (const float*)d_in[5];
    const float* Wk    = (const float*)d_in[6];
    const float* bk    = (const float*)d_in[7];
    float* out = (float*)d_out;

    static bool attr_set = false;
    if (!attr_set) {
        cudaFuncSetAttribute(proj_kernel,
                             cudaFuncAttributeMaxDynamicSharedMemorySize, GEMM_SMEM_BYTES);
        cudaFuncSetAttribute(logits_kernel,
                             cudaFuncAttributeMaxDynamicSharedMemorySize, GEMM_SMEM_BYTES);
        attr_set = true;
    }

    // 1) round inputs (one launch) + round-transpose weights (one launch)
    const int nQK8 = B * L * D / 8;   // 2,097,152
    round_qk<<<dim3(1184, 2), 256>>>(query, key, nQK8);
    round_wT<<<dim3(D / 32, D / 32, 2), 256>>>(Wq, Wk);

    // 2) both projections, one launch (logits-identical B-path)
    proj_kernel<<<dim3(D / 128, (B * L) / 128, 2), 256, GEMM_SMEM_BYTES>>>(bq, bk);

    // 3) masked scaled logits
    logits_kernel<<<dim3(L / 128, L / 128, B), 256, GEMM_SMEM_BYTES>>>(kmask);

    // 4) softmax + query mask
    softmax_kernel<<<(B * L) / 8, 256>>>(qmask, out);
}

// round 17
// speedup vs baseline: 1.0148x; 1.0126x over previous
#include <cuda_runtime.h>
#include <cuda_fp16.h>
#include <mma.h>
#include <cstdint>

using namespace nvcuda;

// Problem constants
constexpr int B = 32;
constexpr int L = 1024;
constexpr int D = 512;
constexpr float NEG_INF = -1000000000.0f;
constexpr float SCALE = 0.04419417382415922f; // 1/sqrt(512)

// __device__ scratch (allocation-guard-legal)
__device__ __half g_Qh[B * L * D];   // half-rounded query input
__device__ __half g_Kh[B * L * D];   // half-rounded key input
__device__ __half g_Wqt[D * D];      // half-rounded Wq^T  (Wt[n][k] = W[k][n])
__device__ __half g_Wkt[D * D];      // half-rounded Wk^T
__device__ __half g_Q[B * L * D];    // relu(q@Wq+bq), half
__device__ __half g_K[B * L * D];    // relu(k@Wk+bk), half
__device__ float  g_S[B * L * L];    // masked scaled logits (fp32)

// ---------------------------------------------------------------------------
// cp.async helpers
// ---------------------------------------------------------------------------
__device__ __forceinline__ void cp_async16(void* smem_dst, const void* gmem_src) {
    unsigned int s = (unsigned int)__cvta_generic_to_shared(smem_dst);
    asm volatile("cp.async.cg.shared.global [%0], [%1], 16;\n" :: "r"(s), "l"(gmem_src));
}
__device__ __forceinline__ void cp_commit() {
    asm volatile("cp.async.commit_group;\n");
}
template <int N>
__device__ __forceinline__ void cp_wait() {
    asm volatile("cp.async.wait_group %0;\n" :: "n"(N));
}

__device__ __forceinline__ uint4 cvt_half8(const float4& a, const float4& b) {
    __half2 h0 = __floats2half2_rn(a.x, a.y);
    __half2 h1 = __floats2half2_rn(a.z, a.w);
    __half2 h2 = __floats2half2_rn(b.x, b.y);
    __half2 h3 = __floats2half2_rn(b.z, b.w);
    uint4 o;
    o.x = *(unsigned int*)&h0; o.y = *(unsigned int*)&h1;
    o.z = *(unsigned int*)&h2; o.w = *(unsigned int*)&h3;
    return o;
}

// ---------------------------------------------------------------------------
// round_qk: both inputs in one launch (grid.y selects query/key)
// ---------------------------------------------------------------------------
__global__ __launch_bounds__(256)
void round_qk(const float* __restrict__ q, const float* __restrict__ k, int n8) {
    const float* src = blockIdx.y == 0 ? q : k;
    __half* dst = blockIdx.y == 0 ? g_Qh : g_Kh;
    int i = blockIdx.x * blockDim.x + threadIdx.x;
    int stride = gridDim.x * blockDim.x;
    for (; i < n8; i += stride) {
        float4 a = ((const float4*)src)[2 * i];
        float4 b = ((const float4*)src)[2 * i + 1];
        ((uint4*)dst)[i] = cvt_half8(a, b);
    }
}

// ---------------------------------------------------------------------------
// round_wT: Wt[n][k] = half_rn(W[k][n]) for both weights (grid.z selects).
// ---------------------------------------------------------------------------
__global__ __launch_bounds__(256)
void round_wT(const float* __restrict__ Wq, const float* __restrict__ Wk) {
    __shared__ float t[32][33];
    const float* W = blockIdx.z == 0 ? Wq : Wk;
    __half* Wt = blockIdx.z == 0 ? g_Wqt : g_Wkt;
    const int bx = blockIdx.x * 32;   // n-tile
    const int by = blockIdx.y * 32;   // k-tile
    const int tx = threadIdx.x & 31;
    const int ty = (threadIdx.x >> 5) * 4;
    #pragma unroll
    for (int i = 0; i < 4; i++)
        t[ty + i][tx] = W[(size_t)(by + ty + i) * D + bx + tx];
    __syncthreads();
    #pragma unroll
    for (int i = 0; i < 4; i++)
        Wt[(size_t)(bx + ty + i) * D + by + tx] = __float2half_rn(t[tx][ty + i]);
}

// ---------------------------------------------------------------------------
// proj (merged, grid.z selects Q/K): out = half_rn(relu(in @ W + bias))
// CTA 128x128, 128 threads (4 warps), WARP TILE 64x64 (16 acc frags).
// 2-stage cp.async, both operands n/k-major staged 128x40, col-major b-frags.
// SMEM (halfs): A0@0, A1@5120, B0@10240, B1@15360; Cs f32 128x132 overlays.
// SMEM = 67584 B, 2 CTAs/SM.
// ---------------------------------------------------------------------------
constexpr int GEMM_SMEM_BYTES = 128 * 132 * 4;  // 67584

__global__ __launch_bounds__(128, 2)
void proj_kernel(const float* __restrict__ bq, const float* __restrict__ bk) {
    extern __shared__ __align__(128) char smem_raw[];
    __half* smh = (__half*)smem_raw;
    float*  Cs  = (float*)smem_raw;   // epilogue overlay

    const bool isQ = (blockIdx.z == 0);
    const __half* in   = isQ ? g_Qh : g_Kh;
    const __half* Wt   = isQ ? g_Wqt : g_Wkt;
    const float*  bias = isQ ? bq : bk;
    __half* out        = isQ ? g_Q : g_K;

    const int tid  = threadIdx.x;
    const int warp = tid >> 5;         // 0..3
    const int m0 = blockIdx.y * 128;
    const int n0 = blockIdx.x * 128;

    const int wr = (warp >> 1) * 64;   // 0 or 64
    const int wc = (warp & 1) * 64;    // 0 or 64

    const __half* Ag = in + (size_t)m0 * D;
    const __half* Bg = Wt + (size_t)n0 * D;

    auto stage = [&](int kt) {
        const int pb = kt & 1;
        const int k0 = kt * 32;
        __half* Ab = smh + pb * 5120;            // 128 x ld40
        __half* Bb = smh + 10240 + pb * 5120;    // 128 x ld40
        #pragma unroll
        for (int i = 0; i < 4; i++) {            // 512 chunks / 128 thr
            int idx = tid + i * 128;
            int r = idx >> 2, c8 = (idx & 3) << 3;
            cp_async16(&Ab[r * 40 + c8], Ag + (size_t)r * D + k0 + c8);
        }
        #pragma unroll
        for (int i = 0; i < 4; i++) {
            int idx = tid + i * 128;
            int r = idx >> 2, c8 = (idx & 3) << 3;
            cp_async16(&Bb[r * 40 + c8], Bg + (size_t)r * D + k0 + c8);
        }
        cp_commit();
    };

    wmma::fragment<wmma::accumulator, 16, 16, 16, float> acc[4][4];
    #pragma unroll
    for (int i = 0; i < 4; i++)
        #pragma unroll
        for (int j = 0; j < 4; j++) wmma::fill_fragment(acc[i][j], 0.0f);

    stage(0);
    for (int kt = 0; kt < 16; kt++) {
        const int pb = kt & 1;
        if (kt < 15) { stage(kt + 1); cp_wait<1>(); }
        else         { cp_wait<0>(); }
        __syncthreads();

        const __half* Ab = smh + pb * 5120;
        const __half* Bb = smh + 10240 + pb * 5120;
        #pragma unroll
        for (int k16 = 0; k16 < 2; k16++) {
            wmma::fragment<wmma::matrix_a, 16, 16, 16, __half, wmma::row_major> a[4];
            #pragma unroll
            for (int i = 0; i < 4; i++)
                wmma::load_matrix_sync(a[i], &Ab[(wr + i * 16) * 40 + k16 * 16], 40);
            #pragma unroll
            for (int j = 0; j < 4; j++) {
                wmma::fragment<wmma::matrix_b, 16, 16, 16, __half, wmma::col_major> bf;
                wmma::load_matrix_sync(bf, &Bb[(wc + j * 16) * 40 + k16 * 16], 40);
                #pragma unroll
                for (int i = 0; i < 4; i++)
                    wmma::mma_sync(acc[i][j], a[i], bf, acc[i][j]);
            }
        }
        __syncthreads();
    }

    // Epilogue: accs -> Cs (f32 overlay) -> bias+relu -> half -> global
    #pragma unroll
    for (int i = 0; i < 4; i++)
        #pragma unroll
        for (int j = 0; j < 4; j++)
            wmma::store_matrix_sync(&Cs[(wr + i * 16) * 132 + wc + j * 16],
                                    acc[i][j], 132, wmma::mem_row_major);
    __syncthreads();

    for (int i = tid; i < 128 * 128 / 8; i += 128) {
        int idx = i << 3;
        int r = idx >> 7, c = idx & 127;
        float4 v0 = *(const float4*)&Cs[r * 132 + c];
        float4 v1 = *(const float4*)&Cs[r * 132 + c + 4];
        const float* bp = &bias[n0 + c];
        float4 u0 = make_float4(fmaxf(v0.x + bp[0], 0.0f), fmaxf(v0.y + bp[1], 0.0f),
                                fmaxf(v0.z + bp[2], 0.0f), fmaxf(v0.w + bp[3], 0.0f));
        float4 u1 = make_float4(fmaxf(v1.x + bp[4], 0.0f), fmaxf(v1.y + bp[5], 0.0f),
                                fmaxf(v1.z + bp[6], 0.0f), fmaxf(v1.w + bp[7], 0.0f));
        *(uint4*)&out[(size_t)(m0 + r) * D + n0 + c] = cvt_half8(u0, u1);
    }
}

// ---------------------------------------------------------------------------
// logits: S[b,m,n] = (Q[b,m,:].K[b,n,:])*SCALE + (key_mask[b,n]?0:NEG)
// CTA 128x128, 128 threads (4 warps), WARP TILE 64x64, 3-stage cp.async.
// SMEM (halfs): Qs0..2 @ {0,5120,10240}, Ks0..2 @ {15360,20480,25600};
// epilogue Cs f32 128x132 overlays. Grid (8,8,32).
// ---------------------------------------------------------------------------
__global__ __launch_bounds__(128, 2)
void logits_kernel(const int* __restrict__ key_mask) {
    extern __shared__ __align__(128) char smem_raw[];
    __half* smh = (__half*)smem_raw;
    float*  Cs  = (float*)smem_raw;

    const int tid  = threadIdx.x;
    const int warp = tid >> 5;
    const int b  = blockIdx.z;
    const int m0 = blockIdx.y * 128;
    const int n0 = blockIdx.x * 128;

    const int wr = (warp >> 1) * 64;
    const int wc = (warp & 1) * 64;

    const __half* Qg = g_Q + ((size_t)b * L + m0) * D;
    const __half* Kg = g_K + ((size_t)b * L + n0) * D;

    auto stage = [&](int kt) {
        const int sb = kt % 3;
        const int k0 = kt * 32;
        __half* Qb = smh + sb * 5120;
        __half* Kb = smh + 15360 + sb * 5120;
        #pragma unroll
        for (int i = 0; i < 4; i++) {
            int idx = tid + i * 128;
            int r = idx >> 2, c8 = (idx & 3) << 3;
            cp_async16(&Qb[r * 40 + c8], Qg + (size_t)r * D + k0 + c8);
        }
        #pragma unroll
        for (int i = 0; i < 4; i++) {
            int idx = tid + i * 128;
            int r = idx >> 2, c8 = (idx & 3) << 3;
            cp_async16(&Kb[r * 40 + c8], Kg + (size_t)r * D + k0 + c8);
        }
        cp_commit();
    };

    wmma::fragment<wmma::accumulator, 16, 16, 16, float> acc[4][4];
    #pragma unroll
    for (int i = 0; i < 4; i++)
        #pragma unroll
        for (int j = 0; j < 4; j++) wmma::fill_fragment(acc[i][j], 0.0f);

    stage(0);
    stage(1);
    for (int kt = 0; kt < 16; kt++) {
        if (kt < 14) { stage(kt + 2); cp_wait<2>(); }
        else if (kt == 14) { cp_wait<1>(); }
        else { cp_wait<0>(); }
        __syncthreads();

        const int sb = kt % 3;
        const __half* Qb = smh + sb * 5120;
        const __half* Kb = smh + 15360 + sb * 5120;
        #pragma unroll
        for (int k16 = 0; k16 < 2; k16++) {
            wmma::fragment<wmma::matrix_a, 16, 16, 16, __half, wmma::row_major> a[4];
            #pragma unroll
            for (int i = 0; i < 4; i++)
                wmma::load_matrix_sync(a[i], &Qb[(wr + i * 16) * 40 + k16 * 16], 40);
            #pragma unroll
            for (int j = 0; j < 4; j++) {
                wmma::fragment<wmma::matrix_b, 16, 16, 16, __half, wmma::col_major> bf;
                wmma::load_matrix_sync(bf, &Kb[(wc + j * 16) * 40 + k16 * 16], 40);
                #pragma unroll
                for (int i = 0; i < 4; i++)
                    wmma::mma_sync(acc[i][j], a[i], bf, acc[i][j]);
            }
        }
        __syncthreads();
    }

    #pragma unroll
    for (int i = 0; i < 4; i++)
        #pragma unroll
        for (int j = 0; j < 4; j++)
            wmma::store_matrix_sync(&Cs[(wr + i * 16) * 132 + wc + j * 16],
                                    acc[i][j], 132, wmma::mem_row_major);
    __syncthreads();

    // Epilogue: scale + key-mask bias -> g_S (fp32)
    const int* km = key_mask + (size_t)b * L + n0;
    for (int i = tid; i < 128 * 128 / 4; i += 128) {
        int idx = i << 2;
        int r = idx >> 7, c = idx & 127;
        float4 v = *(const float4*)&Cs[r * 132 + c];
        v.x = fmaf(v.x, SCALE, km[c + 0] ? 0.0f : NEG_INF);
        v.y = fmaf(v.y, SCALE, km[c + 1] ? 0.0f : NEG_INF);
        v.z = fmaf(v.z, SCALE, km[c + 2] ? 0.0f : NEG_INF);
        v.w = fmaf(v.w, SCALE, km[c + 3] ? 0.0f : NEG_INF);
        *(float4*)&g_S[((size_t)b * L + m0 + r) * L + n0 + c] = v;
    }
}

// ---------------------------------------------------------------------------
// softmax: per-row (1024 keys) register-resident softmax * query_mask
// ---------------------------------------------------------------------------
__global__ __launch_bounds__(256)
void softmax_kernel(const int* __restrict__ query_mask,
                    float* __restrict__ out) {
    const int lane = threadIdx.x & 31;
    const int warp = threadIdx.x >> 5;
    const size_t row = (size_t)blockIdx.x * 8 + warp;

    const float4* srow = (const float4*)(g_S + row * L);
    float4 v[8];
    #pragma unroll
    for (int j = 0; j < 8; j++) v[j] = srow[lane + j * 32];

    float mx = -3.4e38f;
    #pragma unroll
    for (int j = 0; j < 8; j++)
        mx = fmaxf(mx, fmaxf(fmaxf(v[j].x, v[j].y), fmaxf(v[j].z, v[j].w)));
    #pragma unroll
    for (int o = 16; o > 0; o >>= 1) mx = fmaxf(mx, __shfl_xor_sync(0xffffffffu, mx, o));

    float sum = 0.0f;
    #pragma unroll
    for (int j = 0; j < 8; j++) {
        v[j].x = __expf(v[j].x - mx);
        v[j].y = __expf(v[j].y - mx);
        v[j].z = __expf(v[j].z - mx);
        v[j].w = __expf(v[j].w - mx);
        sum += (v[j].x + v[j].y) + (v[j].z + v[j].w);
    }
    #pragma unroll
    for (int o = 16; o > 0; o >>= 1) sum += __shfl_xor_sync(0xffffffffu, sum, o);

    const float inv = (float)query_mask[row] / sum;  // sum >= 1

    float4* orow = (float4*)(out + row * L);
    #pragma unroll
    for (int j = 0; j < 8; j++) {
        v[j].x *= inv; v[j].y *= inv; v[j].z *= inv; v[j].w *= inv;
        orow[lane + j * 32] = v[j];
    }
}

// ---------------------------------------------------------------------------
// kernel_launch — graph-capturable, allocation-free.
// 5 launches: round_qk(0), round_wT(1), proj(2), logits(3)<-ncu, softmax(4).
// ---------------------------------------------------------------------------
extern "C" void kernel_launch(void* const* d_in, const int* in_sizes, int n_in,
                              void* d_out, int out_size) {
    (void)in_sizes; (void)n_in; (void)out_size;
    const float* query = (const float*)d_in[0];
    const float* key   = (const float*)d_in[1];
    const int*   qmask = (const int*)d_in[2];
    const int*   kmask = (const int*)d_in[3];
    const float* Wq    = (const float*)d_in[4];
    const float* bq    = (const float*)d_in[5];
    const float* Wk    = (const float*)d_in[6];
    const float* bk    = (const float*)d_in[7];
    float* out = (float*)d_out;

    static bool attr_set = false;
    if (!attr_set) {
        cudaFuncSetAttribute(proj_kernel,
                             cudaFuncAttributeMaxDynamicSharedMemorySize, GEMM_SMEM_BYTES);
        cudaFuncSetAttribute(logits_kernel,
                             cudaFuncAttributeMaxDynamicSharedMemorySize, GEMM_SMEM_BYTES);
        attr_set = true;
    }

    // 1) round inputs (one launch) + round-transpose weights (one launch)
    const int nQK8 = B * L * D / 8;   // 2,097,152
    round_qk<<<dim3(1184, 2), 256>>>(query, key, nQK8);
    round_wT<<<dim3(D / 32, D / 32, 2), 256>>>(Wq, Wk);

    // 2) both projections, one launch (64x64 warp tiles)
    proj_kernel<<<dim3(D / 128, (B * L) / 128, 2), 128, GEMM_SMEM_BYTES>>>(bq, bk);

    // 3) masked scaled logits (64x64 warp tiles)
    logits_kernel<<<dim3(L / 128, L / 128, B), 128, GEMM_SMEM_BYTES>>>(kmask);

    // 4) softmax + query mask
    softmax_kernel<<<(B * L) / 8, 256>>>(qmask, out);
}